// round 1
// baseline (speedup 1.0000x reference)
#include <cuda_runtime.h>
#include <math.h>

#define NBATCH 64
#define NPTS   500
#define DIM    2048
#define KCL    10
#define NITER  10
#define EPSV   1e-6f
#define SSPLIT 4            // assign-kernel splits per batch
#define ABLK   256          // assign kernel block size

// ---------------- persistent device scratch (no allocs allowed) ----------------
__device__ float g_centroids[NBATCH * KCL * DIM];   // 5.24 MB
__device__ int   g_assign[NBATCH * NPTS];           // 128 KB

// ---------------- packed f32x2 helpers (sm_103a: FFMA2 = 2x FFMA throughput) ----
__device__ __forceinline__ unsigned long long fma2(unsigned long long a,
                                                   unsigned long long b,
                                                   unsigned long long c) {
    unsigned long long d;
    asm("fma.rn.f32x2 %0, %1, %2, %3;" : "=l"(d) : "l"(a), "l"(b), "l"(c));
    return d;
}
__device__ __forceinline__ float2 unpack2(unsigned long long v) {
    float2 r;
    asm("mov.b64 {%0, %1}, %2;" : "=f"(r.x), "=f"(r.y) : "l"(v));
    return r;
}

// ---------------- init: centroids = features[:, :K, :] ----------------
__global__ void init_centroids_kernel(const float* __restrict__ f) {
    int bk = blockIdx.x;            // 0 .. NBATCH*KCL-1
    int b = bk / KCL, k = bk % KCL;
    int d = threadIdx.x * 4;        // 512 threads * 4 = 2048
    float4 v = *(const float4*)(f + ((size_t)(b * NPTS + k)) * DIM + d);
    *(float4*)(g_centroids + ((size_t)(b * KCL + k)) * DIM + d) = v;
}

// ---------------- assignment: argmin_k (0.5|c_k|^2 - f.c_k) ----------------
// grid = NBATCH*SSPLIT, block = 256 (8 warps), 80KB dyn smem, 2 CTAs/SM.
// Warp processes 4 rows at a time; accumulators are f32x2 over d-pairs so
// both f and c load straight into packed regs (zero pack instructions).
__global__ __launch_bounds__(ABLK, 2) void assign_kernel(const float* __restrict__ feats) {
    extern __shared__ float smem[];
    float* sc     = smem;            // KCL * DIM centroids
    float* schalf = smem + KCL * DIM; // KCL  (0.5*|c|^2)

    int b  = blockIdx.x / SSPLIT;
    int sp = blockIdx.x % SSPLIT;
    int tid = threadIdx.x;
    int warp = tid >> 5, lane = tid & 31;

    // load centroids into smem (float4, coalesced)
    const float4* cb4 = (const float4*)(g_centroids + (size_t)b * KCL * DIM);
    for (int i = tid; i < KCL * DIM / 4; i += ABLK)
        ((float4*)sc)[i] = cb4[i];
    __syncthreads();

    // centroid half-norms: warp w handles k = w, w+8
    for (int k = warp; k < KCL; k += 8) {
        float s = 0.f;
        for (int d = lane; d < DIM; d += 32) {
            float c = sc[k * DIM + d];
            s = fmaf(c, c, s);
        }
        #pragma unroll
        for (int off = 16; off; off >>= 1) s += __shfl_xor_sync(0xffffffffu, s, off);
        if (lane == 0) schalf[k] = 0.5f * s;
    }
    __syncthreads();

    const float* fb = feats + (size_t)b * NPTS * DIM;
    int slot = sp * 8 + warp;                 // 0..31 per batch
    for (int g = slot; g < NPTS / 4; g += SSPLIT * 8) {
        int row0 = g * 4;
        const float* r0 = fb + (size_t)(row0 + 0) * DIM;
        const float* r1 = fb + (size_t)(row0 + 1) * DIM;
        const float* r2 = fb + (size_t)(row0 + 2) * DIM;
        const float* r3 = fb + (size_t)(row0 + 3) * DIM;

        unsigned long long acc[KCL][4];
        #pragma unroll
        for (int k = 0; k < KCL; k++)
            #pragma unroll
            for (int r = 0; r < 4; r++) acc[k][r] = 0ull;

        #pragma unroll 1
        for (int ch = 0; ch < DIM / 128; ch++) {
            int d = ch * 128 + lane * 4;
            ulonglong2 f0 = *(const ulonglong2*)(r0 + d);
            ulonglong2 f1 = *(const ulonglong2*)(r1 + d);
            ulonglong2 f2v = *(const ulonglong2*)(r2 + d);
            ulonglong2 f3 = *(const ulonglong2*)(r3 + d);
            #pragma unroll
            for (int k = 0; k < KCL; k++) {
                ulonglong2 c2 = *(const ulonglong2*)(sc + k * DIM + d);
                acc[k][0] = fma2(f0.x, c2.x, acc[k][0]);
                acc[k][0] = fma2(f0.y, c2.y, acc[k][0]);
                acc[k][1] = fma2(f1.x, c2.x, acc[k][1]);
                acc[k][1] = fma2(f1.y, c2.y, acc[k][1]);
                acc[k][2] = fma2(f2v.x, c2.x, acc[k][2]);
                acc[k][2] = fma2(f2v.y, c2.y, acc[k][2]);
                acc[k][3] = fma2(f3.x, c2.x, acc[k][3]);
                acc[k][3] = fma2(f3.y, c2.y, acc[k][3]);
            }
        }

        // reduce: pair-halves then warp butterfly
        float dot[KCL][4];
        #pragma unroll
        for (int k = 0; k < KCL; k++) {
            #pragma unroll
            for (int r = 0; r < 4; r++) {
                float2 v = unpack2(acc[k][r]);
                float s = v.x + v.y;
                #pragma unroll
                for (int off = 16; off; off >>= 1)
                    s += __shfl_xor_sync(0xffffffffu, s, off);
                dot[k][r] = s;
            }
        }

        #pragma unroll
        for (int r = 0; r < 4; r++) {
            if (lane == r) {
                float best = schalf[0] - dot[0][r];
                int bi = 0;
                #pragma unroll
                for (int k = 1; k < KCL; k++) {
                    float s = schalf[k] - dot[k][r];
                    if (s < best) { best = s; bi = k; }
                }
                g_assign[b * NPTS + row0 + r] = bi;
            }
        }
    }
}

// ---------------- centroid update: CTA = (batch, cluster), d-parallel ----------
__global__ __launch_bounds__(512) void update_kernel(const float* __restrict__ feats) {
    __shared__ int sa[NPTS];
    int b = blockIdx.x / KCL, k = blockIdx.x % KCL;
    int tid = threadIdx.x;
    for (int i = tid; i < NPTS; i += 512) sa[i] = g_assign[b * NPTS + i];
    __syncthreads();

    const float* fb = feats + (size_t)b * NPTS * DIM + tid * 4;
    float ax = 0.f, ay = 0.f, az = 0.f, aw = 0.f;
    int cnt = 0;
    #pragma unroll 4
    for (int n = 0; n < NPTS; n++) {
        if (sa[n] == k) {
            cnt++;
            float4 f = *(const float4*)(fb + (size_t)n * DIM);
            ax += f.x; ay += f.y; az += f.z; aw += f.w;
        }
    }
    float inv = 1.0f / (float)(cnt > 1 ? cnt : 1);
    float4 o = make_float4(ax * inv, ay * inv, az * inv, aw * inv);
    *(float4*)(g_centroids + (size_t)(b * KCL + k) * DIM + tid * 4) = o;
}

// ---------------- final GeM pooling ----------------
__global__ __launch_bounds__(512) void final_kernel(const float* __restrict__ feats,
                                                    const float* __restrict__ pp,
                                                    float* __restrict__ out) {
    __shared__ int sa[NPTS];
    int b = blockIdx.x / KCL, k = blockIdx.x % KCL;
    int tid = threadIdx.x;
    for (int i = tid; i < NPTS; i += 512) sa[i] = g_assign[b * NPTS + i];
    __syncthreads();

    float pv = pp[0];
    bool p3 = (pv == 3.0f);
    const float* fb = feats + (size_t)b * NPTS * DIM + tid * 4;

    float ax = 0.f, ay = 0.f, az = 0.f, aw = 0.f;
    int cnt = 0;
    if (p3) {
        #pragma unroll 2
        for (int n = 0; n < NPTS; n++) {
            if (sa[n] == k) {
                cnt++;
                float4 f = *(const float4*)(fb + (size_t)n * DIM);
                float x = fmaxf(f.x, EPSV), y = fmaxf(f.y, EPSV);
                float z = fmaxf(f.z, EPSV), w = fmaxf(f.w, EPSV);
                ax += x * x * x; ay += y * y * y; az += z * z * z; aw += w * w * w;
            }
        }
    } else {
        for (int n = 0; n < NPTS; n++) {
            if (sa[n] == k) {
                cnt++;
                float4 f = *(const float4*)(fb + (size_t)n * DIM);
                ax += powf(fmaxf(f.x, EPSV), pv);
                ay += powf(fmaxf(f.y, EPSV), pv);
                az += powf(fmaxf(f.z, EPSV), pv);
                aw += powf(fmaxf(f.w, EPSV), pv);
            }
        }
    }

    float inv = 1.0f / (float)(cnt > 1 ? cnt : 1);
    size_t oi = (size_t)(b * KCL + k) * DIM + tid * 4;
    float4 o;
    if (cnt > 0) {
        if (p3) {
            o = make_float4(cbrtf(ax * inv), cbrtf(ay * inv),
                            cbrtf(az * inv), cbrtf(aw * inv));
        } else {
            float ip = 1.0f / pv;
            o = make_float4(powf(ax * inv, ip), powf(ay * inv, ip),
                            powf(az * inv, ip), powf(aw * inv, ip));
        }
    } else {
        o = *(const float4*)(g_centroids + oi);  // == 0 per reference semantics
    }
    *(float4*)(out + oi) = o;
}

// ---------------- launch ----------------
extern "C" void kernel_launch(void* const* d_in, const int* in_sizes, int n_in,
                              void* d_out, int out_size) {
    const float* feats = (const float*)d_in[0];
    const float* p     = (const float*)d_in[1];
    float* out         = (float*)d_out;

    const int smem_assign = (KCL * DIM + 16) * sizeof(float);  // ~82 KB
    cudaFuncSetAttribute(assign_kernel,
                         cudaFuncAttributeMaxDynamicSharedMemorySize, smem_assign);

    init_centroids_kernel<<<NBATCH * KCL, 512>>>(feats);
    for (int it = 0; it < NITER; it++) {
        assign_kernel<<<NBATCH * SSPLIT, ABLK, smem_assign>>>(feats);
        update_kernel<<<NBATCH * KCL, 512>>>(feats);
    }
    final_kernel<<<NBATCH * KCL, 512>>>(feats, p, out);
}

// round 2
// speedup vs baseline: 1.3187x; 1.3187x over previous
#include <cuda_runtime.h>
#include <math.h>

#define NBATCH 64
#define NPTS   500
#define DIM    2048
#define KCL    10
#define NITER  10
#define EPSV   1e-6f
#define NSPLIT 2                 // CTAs per batch
#define NROWC  (NPTS / NSPLIT)   // 250 rows per CTA
#define TILE   64                // rows per tile (16 warps * 4)
#define NTILES ((NROWC + TILE - 1) / TILE)  // 4

// ---------------- persistent device scratch ----------------
__device__ float g_centroids[NBATCH * KCL * DIM];          // 5.24 MB
__device__ float g_part[NBATCH * NSPLIT * KCL * DIM];      // 10.5 MB
__device__ int   g_pcnt[NBATCH * NSPLIT * KCL];
__device__ int   g_assign[NBATCH * NPTS];

// ---------------- packed f32x2 helpers ----------------
__device__ __forceinline__ unsigned long long fma2(unsigned long long a,
                                                   unsigned long long b,
                                                   unsigned long long c) {
    unsigned long long d;
    asm("fma.rn.f32x2 %0, %1, %2, %3;" : "=l"(d) : "l"(a), "l"(b), "l"(c));
    return d;
}
__device__ __forceinline__ float2 unpack2(unsigned long long v) {
    float2 r;
    asm("mov.b64 {%0, %1}, %2;" : "=f"(r.x), "=f"(r.y) : "l"(v));
    return r;
}

// ---------------- init: centroids = features[:, :K, :] ----------------
__global__ void init_centroids_kernel(const float* __restrict__ f) {
    int bk = blockIdx.x;
    int b = bk / KCL, k = bk % KCL;
    int d = threadIdx.x * 4;
    float4 v = *(const float4*)(f + ((size_t)(b * NPTS + k)) * DIM + d);
    *(float4*)(g_centroids + ((size_t)(b * KCL + k)) * DIM + d) = v;
}

// FMA block: 10 clusters x 4 rows, packed f32x2
#define FMABLOCK(C0, C1, C2, C3)                                              \
    _Pragma("unroll")                                                         \
    for (int k = 0; k < KCL; k++) {                                           \
        ulonglong2 cc = *(const ulonglong2*)(scd + (size_t)k * DIM);          \
        acc[k][0] = fma2((C0).x, cc.x, acc[k][0]);                            \
        acc[k][0] = fma2((C0).y, cc.y, acc[k][0]);                            \
        acc[k][1] = fma2((C1).x, cc.x, acc[k][1]);                            \
        acc[k][1] = fma2((C1).y, cc.y, acc[k][1]);                            \
        acc[k][2] = fma2((C2).x, cc.x, acc[k][2]);                            \
        acc[k][2] = fma2((C2).y, cc.y, acc[k][2]);                            \
        acc[k][3] = fma2((C3).x, cc.x, acc[k][3]);                            \
        acc[k][3] = fma2((C3).y, cc.y, acc[k][3]);                            \
    }

// ---------------- fused assign + partial-update ----------------
// grid = NBATCH*NSPLIT = 128 (all resident, 1 CTA/SM), block = 512.
// Per 64-row tile: phase A assigns (dot products, centroids in smem),
// counting-sort by cluster (warp-0 ballots, deterministic), phase B
// accumulates per-cluster partial sums while rows are hot in L2.
__global__ __launch_bounds__(512, 1) void iter_kernel(const float* __restrict__ feats) {
    extern __shared__ float smem[];
    float* sc      = smem;                    // [KCL][DIM] centroids
    float* sacc    = smem + KCL * DIM;        // [KCL][DIM] accumulators
    float* schalf  = sacc + KCL * DIM;        // [16]
    int*   sa      = (int*)(schalf + 16);     // [TILE] tile assignments
    int*   ssorted = sa + TILE;               // [TILE]
    int*   soff    = ssorted + TILE;          // [12]  tile cluster offsets
    int*   srun    = soff + 12;               // [10]
    int*   scnt    = srun + 10;               // [10]  CTA running counts

    int b = blockIdx.x >> 1, sp = blockIdx.x & 1;
    int tid = threadIdx.x, warp = tid >> 5, lane = tid & 31;

    const float4* cb4 = (const float4*)(g_centroids + (size_t)b * KCL * DIM);
    float4 z4 = make_float4(0.f, 0.f, 0.f, 0.f);
    for (int i = tid; i < KCL * DIM / 4; i += 512) {
        ((float4*)sc)[i] = cb4[i];
        ((float4*)sacc)[i] = z4;
    }
    if (tid < KCL) scnt[tid] = 0;
    __syncthreads();

    if (warp < KCL) {
        float s = 0.f;
        for (int d = lane; d < DIM; d += 32) {
            float c = sc[warp * DIM + d];
            s = fmaf(c, c, s);
        }
        #pragma unroll
        for (int o = 16; o; o >>= 1) s += __shfl_xor_sync(0xffffffffu, s, o);
        if (lane == 0) schalf[warp] = 0.5f * s;
    }
    __syncthreads();

    const float* fb = feats + ((size_t)b * NPTS + (size_t)sp * NROWC) * DIM;
    int gabase = b * NPTS + sp * NROWC;
    int mywd = warp * 128 + lane * 4;         // phase-B d-slice

    for (int tile = 0; tile < NTILES; tile++) {
        int tbase = tile * TILE;
        int nrows = NROWC - tbase; if (nrows > TILE) nrows = TILE;

        // ---------- phase A: assign 4 rows per warp ----------
        int r0i = tbase + warp * 4;
        int i0 = r0i + 0; if (i0 > NROWC - 1) i0 = NROWC - 1;
        int i1 = r0i + 1; if (i1 > NROWC - 1) i1 = NROWC - 1;
        int i2 = r0i + 2; if (i2 > NROWC - 1) i2 = NROWC - 1;
        int i3 = r0i + 3; if (i3 > NROWC - 1) i3 = NROWC - 1;
        const float* p0 = fb + (size_t)i0 * DIM + lane * 4;
        const float* p1 = fb + (size_t)i1 * DIM + lane * 4;
        const float* p2 = fb + (size_t)i2 * DIM + lane * 4;
        const float* p3 = fb + (size_t)i3 * DIM + lane * 4;

        unsigned long long acc[KCL][4];
        #pragma unroll
        for (int k = 0; k < KCL; k++)
            #pragma unroll
            for (int r = 0; r < 4; r++) acc[k][r] = 0ull;

        // double-buffered: loads for chunk ch+1 issue before FMAs of ch retire
        ulonglong2 c0 = *(const ulonglong2*)p0;
        ulonglong2 c1 = *(const ulonglong2*)p1;
        ulonglong2 c2 = *(const ulonglong2*)p2;
        ulonglong2 c3 = *(const ulonglong2*)p3;
        #pragma unroll 1
        for (int ch = 0; ch < 15; ch++) {
            int nofs = (ch + 1) * 128;
            ulonglong2 n0 = *(const ulonglong2*)(p0 + nofs);
            ulonglong2 n1 = *(const ulonglong2*)(p1 + nofs);
            ulonglong2 n2 = *(const ulonglong2*)(p2 + nofs);
            ulonglong2 n3 = *(const ulonglong2*)(p3 + nofs);
            const float* scd = sc + ch * 128 + lane * 4;
            FMABLOCK(c0, c1, c2, c3);
            c0 = n0; c1 = n1; c2 = n2; c3 = n3;
        }
        {
            const float* scd = sc + 15 * 128 + lane * 4;
            FMABLOCK(c0, c1, c2, c3);
        }

        // reduce + argmin
        float dot[KCL][4];
        #pragma unroll
        for (int k = 0; k < KCL; k++) {
            #pragma unroll
            for (int r = 0; r < 4; r++) {
                float2 v = unpack2(acc[k][r]);
                float s = v.x + v.y;
                #pragma unroll
                for (int o = 16; o; o >>= 1)
                    s += __shfl_xor_sync(0xffffffffu, s, o);
                dot[k][r] = s;
            }
        }
        #pragma unroll
        for (int r = 0; r < 4; r++) {
            if (lane == r && (r0i + r) < NROWC) {
                float best = schalf[0] - dot[0][r];
                int bi = 0;
                #pragma unroll
                for (int k = 1; k < KCL; k++) {
                    float s = schalf[k] - dot[k][r];
                    if (s < best) { best = s; bi = k; }
                }
                sa[warp * 4 + r] = bi;
                g_assign[gabase + r0i + r] = bi;
            }
        }
        __syncthreads();

        // ---------- counting sort of the tile (warp 0, deterministic) ----------
        if (warp == 0) {
            int mycnt = 0;
            #pragma unroll
            for (int p = 0; p < 2; p++) {
                int n = p * 32 + lane;
                int a = (n < nrows) ? sa[n] : -1;
                #pragma unroll
                for (int k = 0; k < KCL; k++) {
                    unsigned m = __ballot_sync(0xffffffffu, a == k);
                    if (lane == k) mycnt += __popc(m);
                }
            }
            int v = (lane < KCL) ? mycnt : 0;
            #pragma unroll
            for (int o = 1; o < 16; o <<= 1) {
                int t = __shfl_up_sync(0xffffffffu, v, o);
                if (lane >= o) v += t;
            }
            int excl = v - ((lane < KCL) ? mycnt : 0);
            if (lane < KCL) { soff[lane] = excl; srun[lane] = excl; scnt[lane] += mycnt; }
            if (lane == KCL - 1) soff[KCL] = v;
            __syncwarp();
            #pragma unroll
            for (int p = 0; p < 2; p++) {
                int n = p * 32 + lane;
                int a = (n < nrows) ? sa[n] : -1;
                unsigned mybal = 0;
                #pragma unroll
                for (int k = 0; k < KCL; k++) {
                    unsigned m = __ballot_sync(0xffffffffu, a == k);
                    if (a == k) mybal = m;
                }
                if (a >= 0) {
                    int rank = __popc(mybal & ((1u << lane) - 1u));
                    ssorted[srun[a] + rank] = n;
                    if (rank == __popc(mybal) - 1) srun[a] += rank + 1;
                }
                __syncwarp();
            }
        }
        __syncthreads();

        // ---------- phase B: per-cluster accumulate (rows hot in L2) ----------
        {
            const float* fsl = fb + (size_t)tbase * DIM + mywd;
            #pragma unroll
            for (int k = 0; k < KCL; k++) {
                int s0 = soff[k], s1 = soff[k + 1];
                if (s0 == s1) continue;
                float4 a4 = z4;
                int idx = s0;
                for (; idx + 2 <= s1; idx += 2) {
                    int na = ssorted[idx], nb = ssorted[idx + 1];
                    float4 fa = *(const float4*)(fsl + (size_t)na * DIM);
                    float4 fc = *(const float4*)(fsl + (size_t)nb * DIM);
                    a4.x += fa.x; a4.y += fa.y; a4.z += fa.z; a4.w += fa.w;
                    a4.x += fc.x; a4.y += fc.y; a4.z += fc.z; a4.w += fc.w;
                }
                if (idx < s1) {
                    int na = ssorted[idx];
                    float4 fa = *(const float4*)(fsl + (size_t)na * DIM);
                    a4.x += fa.x; a4.y += fa.y; a4.z += fa.z; a4.w += fa.w;
                }
                float4* ap = (float4*)(sacc + (size_t)k * DIM + mywd);
                float4 cur = *ap;
                cur.x += a4.x; cur.y += a4.y; cur.z += a4.z; cur.w += a4.w;
                *ap = cur;
            }
        }
        __syncthreads();
    }

    // write partial sums + counts
    float* pb = g_part + (size_t)blockIdx.x * KCL * DIM;
    for (int i = tid; i < KCL * DIM / 4; i += 512)
        ((float4*)pb)[i] = ((const float4*)sacc)[i];
    if (tid < KCL) g_pcnt[blockIdx.x * KCL + tid] = scnt[tid];
}

// ---------------- reduce partials -> new centroids ----------------
__global__ __launch_bounds__(512) void reduce_kernel() {
    int bk = blockIdx.x;
    int b = bk / KCL, k = bk % KCL;
    int c = g_pcnt[(b * NSPLIT + 0) * KCL + k] + g_pcnt[(b * NSPLIT + 1) * KCL + k];
    float inv = 1.0f / (float)(c > 1 ? c : 1);
    int d = threadIdx.x * 4;
    float4 a = *(const float4*)(g_part + ((size_t)(b * NSPLIT + 0) * KCL + k) * DIM + d);
    float4 e = *(const float4*)(g_part + ((size_t)(b * NSPLIT + 1) * KCL + k) * DIM + d);
    float4 o = make_float4((a.x + e.x) * inv, (a.y + e.y) * inv,
                           (a.z + e.z) * inv, (a.w + e.w) * inv);
    *(float4*)(g_centroids + ((size_t)b * KCL + k) * DIM + d) = o;
}

// ---------------- final GeM pooling ----------------
__global__ __launch_bounds__(512) void final_kernel(const float* __restrict__ feats,
                                                    const float* __restrict__ pp,
                                                    float* __restrict__ out) {
    __shared__ int sa[NPTS];
    int b = blockIdx.x / KCL, k = blockIdx.x % KCL;
    int tid = threadIdx.x;
    for (int i = tid; i < NPTS; i += 512) sa[i] = g_assign[b * NPTS + i];
    __syncthreads();

    float pv = pp[0];
    bool p3 = (pv == 3.0f);
    const float* fb = feats + (size_t)b * NPTS * DIM + tid * 4;

    float ax = 0.f, ay = 0.f, az = 0.f, aw = 0.f;
    int cnt = 0;
    if (p3) {
        #pragma unroll 2
        for (int n = 0; n < NPTS; n++) {
            if (sa[n] == k) {
                cnt++;
                float4 f = *(const float4*)(fb + (size_t)n * DIM);
                float x = fmaxf(f.x, EPSV), y = fmaxf(f.y, EPSV);
                float z = fmaxf(f.z, EPSV), w = fmaxf(f.w, EPSV);
                ax += x * x * x; ay += y * y * y; az += z * z * z; aw += w * w * w;
            }
        }
    } else {
        for (int n = 0; n < NPTS; n++) {
            if (sa[n] == k) {
                cnt++;
                float4 f = *(const float4*)(fb + (size_t)n * DIM);
                ax += powf(fmaxf(f.x, EPSV), pv);
                ay += powf(fmaxf(f.y, EPSV), pv);
                az += powf(fmaxf(f.z, EPSV), pv);
                aw += powf(fmaxf(f.w, EPSV), pv);
            }
        }
    }

    float inv = 1.0f / (float)(cnt > 1 ? cnt : 1);
    size_t oi = (size_t)(b * KCL + k) * DIM + tid * 4;
    float4 o;
    if (cnt > 0) {
        if (p3) {
            o = make_float4(cbrtf(ax * inv), cbrtf(ay * inv),
                            cbrtf(az * inv), cbrtf(aw * inv));
        } else {
            float ip = 1.0f / pv;
            o = make_float4(powf(ax * inv, ip), powf(ay * inv, ip),
                            powf(az * inv, ip), powf(aw * inv, ip));
        }
    } else {
        o = *(const float4*)(g_centroids + oi);
    }
    *(float4*)(out + oi) = o;
}

// ---------------- launch ----------------
extern "C" void kernel_launch(void* const* d_in, const int* in_sizes, int n_in,
                              void* d_out, int out_size) {
    const float* feats = (const float*)d_in[0];
    const float* p     = (const float*)d_in[1];
    float* out         = (float*)d_out;

    const int smem_iter = (2 * KCL * DIM + 16) * sizeof(float)
                        + (TILE + TILE + 12 + 10 + 10) * sizeof(int);
    cudaFuncSetAttribute(iter_kernel,
                         cudaFuncAttributeMaxDynamicSharedMemorySize, smem_iter);

    init_centroids_kernel<<<NBATCH * KCL, 512>>>(feats);
    for (int it = 0; it < NITER; it++) {
        iter_kernel<<<NBATCH * NSPLIT, 512, smem_iter>>>(feats);
        reduce_kernel<<<NBATCH * KCL, 512>>>();
    }
    final_kernel<<<NBATCH * KCL, 512>>>(feats, p, out);
}